// round 17
// baseline (speedup 1.0000x reference)
#include <cuda_runtime.h>

// Problem constants
#define TT 1024   // T: tickers / states
#define MM 8      // M: mesa rank
#define NN 32768  // N: samples
#define DD 32     // D: input dim
#define SS 2177   // S = H*D + H + O*H + O
#define SP 2192   // padded state row stride (float4-aligned)
#define CAP 128   // bucket capacity per ticker

// Fused grid layout (all 32-thread blocks)
#define PREP_B 2304            // 32 ticker-tiles x 72 d-blocks (32 d each)
#define SCAT_B 256             // 256 x 32 threads x int4 = 32768 samples
#define COMP_B 1024            // one block per ticker
#define SCAT_OFF PREP_B
#define COMP_OFF (PREP_B + SCAT_B)
#define GRID_B (PREP_B + SCAT_B + COMP_B)

// Scratch (__device__ globals, zero-initialized at load; every flag/counter
// is returned to 0 by the end of each run -> replay-invariant).
__device__ int   d_count[TT];
__device__ int   d_bucket[TT * CAP];
__device__ float d_states[TT * SP];   // rows in PERMUTED (j*64+h) order
__device__ int   d_tile_done[32];     // 72 increments per 32-ticker tile
__device__ int   d_scat_done;         // 256 increments
__device__ int   d_tile_cons[32];     // 32 consumers per tile; last resets
__device__ int   d_scat_cons;         // 1024 consumers; last resets

__device__ __forceinline__ unsigned long long fma2(
    unsigned long long a, unsigned long long b, unsigned long long c) {
    unsigned long long d;
    asm("fma.rn.f32x2 %0, %1, %2, %3;" : "=l"(d) : "l"(a), "l"(b), "l"(c));
    return d;
}
__device__ __forceinline__ unsigned long long dup2(float v) {
    unsigned long long d;
    asm("mov.b64 %0, {%1, %1};" : "=l"(d) : "f"(v));
    return d;
}

// ---------------------------------------------------------------------------
// One fused kernel. Producer blocks flag completion; consumer (compute)
// blocks spin on the flags, so state-building / scatter overlap with the
// compute ramp instead of serializing behind a launch boundary.
// Prep & compute inner code are the proven R6-prep / R5-compute bodies.
// ---------------------------------------------------------------------------
__global__ __launch_bounds__(32) void k_fused(
    const float* __restrict__ x,
    const int*   __restrict__ ticker,
    const float* __restrict__ mesa,   // (M, T)
    const float* __restrict__ meta,   // (S, M)
    const float* __restrict__ bias,   // (S,)
    const float* __restrict__ base,   // (S,)
    float* __restrict__ out)          // (N,)
{
    __shared__ __align__(16) float  s_w[2180];
    __shared__ float  s_x[32 * 33];
    __shared__ float4 sc4[32][2];

    int b    = blockIdx.x;
    int lane = threadIdx.x;

    if (b < PREP_B) {
        // ---- state build: tile tt (32 tickers), d-block dblk (32 d) ----
        int tt = b / 72, dblk = b % 72;
        int t0 = tt * 32;
        // mesa coeffs for 32 tickers: 256 floats, 8 per thread
#pragma unroll
        for (int r = 0; r < 8; r++)
            ((float*)sc4)[lane * 8 + r] = mesa[r * TT + t0 + lane];
        __syncwarp();

        int d = dblk * 32 + lane;            // destination index, 0..2303
        if (d < SS) {
            int s;
            if (d < 2048) {                  // w1: d = j*64+h <-> s = h*32+j
                int h = d & 63, j = d >> 6;
                s = h * 32 + j;
            } else {
                s = d;                       // tail: identity
            }
            const float4* m4 = (const float4*)(meta + s * MM);
            float4 a = m4[0], bq = m4[1];
            float bb = base[s] + bias[s];
#pragma unroll
            for (int i = 0; i < 32; i++) {
                float4 c0 = sc4[i][0];       // broadcast LDS.128
                float4 c1 = sc4[i][1];
                float v = bb
                    + c0.x * a.x + c0.y * a.y + c0.z * a.z + c0.w * a.w
                    + c1.x * bq.x + c1.y * bq.y + c1.z * bq.z + c1.w * bq.w;
                d_states[(t0 + i) * SP + d] = v;   // coalesced over d
            }
        }
        __syncwarp();
        __threadfence();                     // data before flag
        if (lane == 0) atomicAdd(&d_tile_done[tt], 1);
    } else if (b < COMP_OFF) {
        // ---- scatter: bucket samples by ticker ----
        int idx = (b - SCAT_OFF) * 32 + lane;      // int4 index < 8192
        int4 v = ((const int4*)ticker)[idx];
        int n0 = idx * 4;
        int p;
        p = atomicAdd(&d_count[v.x], 1); if (p < CAP) d_bucket[v.x * CAP + p] = n0;
        p = atomicAdd(&d_count[v.y], 1); if (p < CAP) d_bucket[v.y * CAP + p] = n0 + 1;
        p = atomicAdd(&d_count[v.z], 1); if (p < CAP) d_bucket[v.z * CAP + p] = n0 + 2;
        p = atomicAdd(&d_count[v.w], 1); if (p < CAP) d_bucket[v.w * CAP + p] = n0 + 3;
        __syncwarp();
        __threadfence();
        if (lane == 0) atomicAdd(&d_scat_done, 1);
    } else {
        // ---- compute: one warp per ticker (exact R5 body) ----
        int t  = b - COMP_OFF;
        int tt = t >> 5;

        if (lane == 0) {                     // wait for my tile + scatter
            while (*(volatile int*)&d_tile_done[tt] < 72) __nanosleep(64);
            while (*(volatile int*)&d_scat_done < SCAT_B) __nanosleep(64);
        }
        __syncwarp();
        __threadfence();                     // acquire: flags before data

        // Coalesced copy of the permuted state row (545 float4).
        const float4* row4 = (const float4*)(d_states + (size_t)t * SP);
        float4* s_w4 = (float4*)s_w;
#pragma unroll
        for (int i = 0; i < 18; i++) {
            int idx = lane + i * 32;
            if (idx < 545) s_w4[idx] = row4[idx];
        }

        int cnt = 0;
        if (lane == 0) { cnt = d_count[t]; d_count[t] = 0; }
        cnt = __shfl_sync(0xffffffffu, cnt, 0);
        if (cnt > CAP) cnt = CAP;
        __syncwarp();

        if (cnt > 0) {
            const unsigned long long* b1p =
                (const unsigned long long*)(s_w + 2048);   // b1 as f32x2 pairs
            float b2 = s_w[2176];

            for (int base2 = 0; base2 < cnt; base2 += 32) {
                int idx = base2 + lane;
                bool valid = idx < cnt;
                int n = d_bucket[t * CAP + (valid ? idx : cnt - 1)];

                __syncwarp();   // previous pass finished reading s_x
#pragma unroll
                for (int k = 0; k < 32; k++) {
                    int nk = __shfl_sync(0xffffffffu, n, k);
                    s_x[k * 33 + lane] = x[nk * DD + lane];   // coalesced rows
                }
                __syncwarp();

                unsigned long long acc[32];
#pragma unroll
                for (int hp = 0; hp < 32; hp++) acc[hp] = b1p[hp];

#pragma unroll 8
                for (int j = 0; j < 32; j++) {
                    float xj = s_x[lane * 33 + j];    // conflict-free scalar LDS
                    unsigned long long xd = dup2(xj);
                    const ulonglong2* wr = (const ulonglong2*)(s_w + j * 64);
#pragma unroll
                    for (int hq = 0; hq < 16; hq++) {
                        ulonglong2 w = wr[hq];        // broadcast LDS.128
                        acc[2 * hq]     = fma2(w.x, xd, acc[2 * hq]);
                        acc[2 * hq + 1] = fma2(w.y, xd, acc[2 * hq + 1]);
                    }
                }

                float o = b2;
#pragma unroll
                for (int hp = 0; hp < 32; hp++) {
                    float lo = __uint_as_float((unsigned)(acc[hp] & 0xffffffffu));
                    float hi = __uint_as_float((unsigned)(acc[hp] >> 32));
                    o += fmaxf(lo, 0.f) * s_w[2112 + 2 * hp]
                       + fmaxf(hi, 0.f) * s_w[2112 + 2 * hp + 1];
                }
                if (valid) out[n] = o;
            }
        }

        // Flag-reset bookkeeping: the LAST consumer of each flag zeroes it,
        // restoring the launch-time state for the next graph replay. Safe:
        // a consumer increments only after passing its spin, so cons==max
        // implies every spinner already passed.
        if (lane == 0) {
            int c = atomicAdd(&d_tile_cons[tt], 1);
            if (c == 31) { d_tile_cons[tt] = 0; d_tile_done[tt] = 0; }
            int s = atomicAdd(&d_scat_cons, 1);
            if (s == COMP_B - 1) { d_scat_cons = 0; d_scat_done = 0; }
        }
    }
}

extern "C" void kernel_launch(void* const* d_in, const int* in_sizes, int n_in,
                              void* d_out, int out_size) {
    const float* x    = (const float*)d_in[0];
    const int*   tick = (const int*)d_in[1];
    const float* mesa = (const float*)d_in[2];   // (M, T)
    const float* meta = (const float*)d_in[3];   // (S, M)
    const float* bias = (const float*)d_in[4];   // (S,)
    const float* base = (const float*)d_in[5];   // (S,)
    float* out = (float*)d_out;                  // (N, 1) float32

    k_fused<<<GRID_B, 32>>>(x, tick, mesa, meta, bias, base, out);
}